// round 16
// baseline (speedup 1.0000x reference)
#include <cuda_runtime.h>
#include <cuda_bf16.h>
#include <cstdint>

#define NEG_SLOPE 0.2f
#define STEP (2.0f / 255.0f)

typedef unsigned long long ull;

__device__ float g_asrc[131072];
__device__ float g_adst[131072];

#define FMA2(d, a, b, c) \
    asm("fma.rn.f32x2 %0, %1, %2, %3;" : "=l"(d) : "l"(a), "l"(b), "l"(c))
#define DUP2(d, s) \
    asm("mov.b64 %0, {%1, %1};" : "=l"(d) : "r"(__float_as_uint(s)))
#define UNPACK2(lo, hi, s) do { \
    unsigned _ulo, _uhi; \
    asm("mov.b64 {%0, %1}, %2;" : "=r"(_ulo), "=r"(_uhi) : "l"(s)); \
    lo = __uint_as_float(_ulo); hi = __uint_as_float(_uhi); } while (0)

// ---------------------------------------------------------------------------
// K1: per-node a_src = xg.(W@att_src), a_dst = xg.(W@att_dst)   (unchanged)
// ---------------------------------------------------------------------------
__global__ __launch_bounds__(256) void gat_k1(
    const float* __restrict__ x,
    const float* __restrict__ pos_w,
    const float* __restrict__ pos_b,
    const float* __restrict__ lin_w,
    const float* __restrict__ att_src,
    const float* __restrict__ att_dst)
{
    __shared__ float swd[128];
    __shared__ float as_s[64], ad_s[64];
    __shared__ float pw0[64], pw1[64], pb_s[64];
    __shared__ float sc[6];

    const int tid = threadIdx.x;
    const int row = blockIdx.x;
    const int b = row >> 8;
    const int y = row & 255;

    if (tid < 64) {
        as_s[tid] = att_src[tid];
        ad_s[tid] = att_dst[tid];
        pw0[tid]  = pos_w[tid];
        pw1[tid]  = pos_w[64 + tid];
        pb_s[tid] = pos_b[tid];
    }
    __syncthreads();

    if (tid < 64) {
        float s = 0.0f, d = 0.0f;
        const float* lw = lin_w + tid * 64;
        #pragma unroll 8
        for (int co = 0; co < 64; co++) {
            float w = lw[co];
            s = fmaf(w, as_s[co], s);
            d = fmaf(w, ad_s[co], d);
        }
        swd[2 * tid]     = s;
        swd[2 * tid + 1] = d;
    }
    __syncthreads();

    if (tid < 6) {
        const int which = tid % 3;
        const int off   = (tid < 3) ? 0 : 1;
        const float* pv = (which == 0) ? pw0 : (which == 1) ? pw1 : pb_s;
        float acc = 0.0f;
        #pragma unroll 8
        for (int c = 0; c < 64; c++)
            acc = fmaf(pv[c], swd[2 * c + off], acc);
        sc[tid] = acc;
    }
    __syncthreads();

    const float py = -1.0f + (float)y * STEP;
    const float px = -1.0f + (float)tid * STEP;

    ull acc2 = 0ULL;
    const float* xp = x + (((size_t)b << 22) | ((size_t)y << 8)) + tid;
    const ull* wp = (const ull*)swd;
    #pragma unroll 8
    for (int c = 0; c < 64; c++) {
        float v = xp[(size_t)c << 16];
        ull vv; DUP2(vv, v);
        FMA2(acc2, vv, wp[c], acc2);
    }
    float s, d;
    UNPACK2(s, d, acc2);
    s += fmaf(py, sc[0], fmaf(px, sc[1], sc[2]));
    d += fmaf(py, sc[3], fmaf(px, sc[4], sc[5]));

    const int node = (b << 16) + (y << 8) + tid;
    g_asrc[node] = s;
    g_adst[node] = d;
}

// ---------------------------------------------------------------------------
// mma helpers (base PTX, sm_80+)
// ---------------------------------------------------------------------------
__device__ __forceinline__ uint32_t smem_u32(const void* p) {
    uint32_t r;
    asm("{ .reg .u64 t; cvta.to.shared.u64 t, %1; cvt.u32.u64 %0, t; }"
        : "=r"(r) : "l"(p));
    return r;
}
__device__ __forceinline__ void ldm_x4(uint32_t* r, uint32_t a) {
    asm volatile("ldmatrix.sync.aligned.m8n8.x4.shared.b16 {%0,%1,%2,%3}, [%4];"
        : "=r"(r[0]), "=r"(r[1]), "=r"(r[2]), "=r"(r[3]) : "r"(a));
}
__device__ __forceinline__ void ldm_x4_t(uint32_t* r, uint32_t a) {
    asm volatile("ldmatrix.sync.aligned.m8n8.x4.trans.shared.b16 {%0,%1,%2,%3}, [%4];"
        : "=r"(r[0]), "=r"(r[1]), "=r"(r[2]), "=r"(r[3]) : "r"(a));
}
__device__ __forceinline__ void mma16816(float* c, const uint32_t* a,
                                         uint32_t b0, uint32_t b1) {
    asm volatile(
        "mma.sync.aligned.m16n8k16.row.col.f32.bf16.bf16.f32 "
        "{%0,%1,%2,%3}, {%4,%5,%6,%7}, {%8,%9}, {%0,%1,%2,%3};"
        : "+f"(c[0]), "+f"(c[1]), "+f"(c[2]), "+f"(c[3])
        : "r"(a[0]), "r"(a[1]), "r"(a[2]), "r"(a[3]), "r"(b0), "r"(b1));
}

#define ZPITCH 272   // z tiles [c=64][node=128] bf16: 256B data + 16B pad
#define WPITCH 144   // W tiles [co=64][k=64] bf16: 128B data + 16B pad

// ---------------------------------------------------------------------------
// K2: fused, 2-ROW TILES, 2 TILES PER BLOCK (single-wave grid of 512).
//   Per tile: thread = (x, 16 ch, 2 y rows); 12 LDG/channel -> 2 outputs;
//   z split bf16 hi/lo -> zh/zl tiles; HMMA GEMM; direct-STG epilogue.
//   W hi/lo staged once, reused by both tiles.
// ---------------------------------------------------------------------------
__global__ __launch_bounds__(256) void gat_k2(
    const float* __restrict__ x,
    const float* __restrict__ lin_w,
    const float* __restrict__ pos_w,
    const float* __restrict__ pos_b,
    const float* __restrict__ bias,
    float* __restrict__ out)
{
    __shared__ __align__(16) char tileblob[2 * 64 * ZPITCH];  // zh, zl
    __shared__ __align__(16) char wblob[2 * 64 * WPITCH];     // Wh, Wl
    __shared__ float pw0[64], pw1[64], pb_s[64], b_s[64];

    const int tid  = threadIdx.x;
    const int lane = tid & 31;
    const int wid  = tid >> 5;

    char* zh_c = tileblob;
    char* zl_c = tileblob + 64 * ZPITCH;
    char* wh_c = wblob;
    char* wl_c = wblob + 64 * WPITCH;

    if (tid < 64) {
        pw0[tid]  = pos_w[tid];
        pw1[tid]  = pos_w[64 + tid];
        pb_s[tid] = pos_b[tid];
        b_s[tid]  = bias[tid];
    }

    // ---- stage W hi/lo once: Wh/Wl[co][k] ----
    {
        const int co = tid & 63;
        const int kq = tid >> 6;
        const float* wp = lin_w + co;
        #pragma unroll
        for (int j = 0; j < 8; j++) {
            const int k0 = kq * 16 + 2 * j;
            float w0 = wp[(size_t)k0 * 64];
            float w1 = wp[(size_t)(k0 + 1) * 64];
            __nv_bfloat162 h = __float22bfloat162_rn(make_float2(w0, w1));
            *(uint32_t*)(wh_c + co * WPITCH + k0 * 2) = *(uint32_t*)&h;
            float r0 = w0 - __bfloat162float(h.x);
            float r1 = w1 - __bfloat162float(h.y);
            __nv_bfloat162 l = __float22bfloat162_rn(make_float2(r0, r1));
            *(uint32_t*)(wl_c + co * WPITCH + k0 * 2) = *(uint32_t*)&l;
        }
    }

    // geometry constants (per thread, tile-independent parts)
    const int q  = tid >> 6;            // channel quarter (16 ch)
    const int xl = tid & 63;            // x within tile

    const uint32_t zh_b = smem_u32(zh_c);
    const uint32_t zl_b = smem_u32(zl_c);
    const uint32_t wh_b = smem_u32(wh_c);
    const uint32_t wl_b = smem_u32(wl_c);

    const int m0 = (wid & 3) << 4;
    const int nb = (wid >> 2) << 6;
    const uint32_t w_row = (uint32_t)(m0 + (lane & 15)) * WPITCH;
    const uint32_t w_kad = ((lane >> 4) << 3) * 2;
    const uint32_t z_kro = (uint32_t)(lane & 15) * ZPITCH;
    const uint32_t z_nad = ((lane >> 4) << 3) * 2;

    #pragma unroll 1
    for (int it = 0; it < 2; it++) {
        const int blk = blockIdx.x + it * 512;   // tile id 0..1023
        const int b   = blk >> 9;
        const int rem = blk & 511;               // 128 y-pairs * 4 x-tiles
        const int y0  = (rem >> 2) << 1;
        const int x0g = (rem & 3) << 6;
        const int xd  = x0g + xl;

        // ---- alpha for both rows (regs), from direct LDG ----
        float alpha0[9], alpha1[9];
        {
            float as_v[4][3];
            #pragma unroll
            for (int rr = 0; rr < 4; rr++) {
                const int yy = y0 - 1 + rr;
                const bool rok = (unsigned)yy < 256u;
                #pragma unroll
                for (int cx = 0; cx < 3; cx++) {
                    const int xs = xd - 1 + cx;
                    float v = -1e30f;
                    if (rok && (unsigned)xs < 256u)
                        v = g_asrc[(b << 16) + (yy << 8) + xs];
                    as_v[rr][cx] = v;
                }
            }
            const float ad0 = g_adst[(b << 16) + (y0 << 8) + xd];
            const float ad1 = g_adst[(b << 16) + ((y0 + 1) << 8) + xd];

            float m0f = -1e30f, m1f = -1e30f;
            #pragma unroll
            for (int ry = 0; ry < 3; ry++) {
                #pragma unroll
                for (int cx = 0; cx < 3; cx++) {
                    float e0 = as_v[ry][cx] + ad0;
                    e0 = (e0 >= 0.0f) ? e0 : NEG_SLOPE * e0;
                    alpha0[ry * 3 + cx] = e0;
                    m0f = fmaxf(m0f, e0);
                    float e1 = as_v[ry + 1][cx] + ad1;
                    e1 = (e1 >= 0.0f) ? e1 : NEG_SLOPE * e1;
                    alpha1[ry * 3 + cx] = e1;
                    m1f = fmaxf(m1f, e1);
                }
            }
            float s0 = 0.0f, s1 = 0.0f;
            #pragma unroll
            for (int j = 0; j < 9; j++) {
                float p0 = expf(alpha0[j] - m0f);
                float p1 = expf(alpha1[j] - m1f);
                alpha0[j] = p0; alpha1[j] = p1;
                s0 += p0; s1 += p1;
            }
            const float i0 = 1.0f / s0, i1 = 1.0f / s1;
            #pragma unroll
            for (int j = 0; j < 9; j++) { alpha0[j] *= i0; alpha1[j] *= i1; }
        }

        // ---- PE hoist for both rows ----
        float spy0 = 0.0f, spx0 = 0.0f, spy1 = 0.0f, spx1 = 0.0f;
        #pragma unroll
        for (int ry = 0; ry < 3; ry++) {
            const float py0v = -1.0f + (float)(y0 - 1 + ry) * STEP;
            const float py1v = -1.0f + (float)(y0 + ry) * STEP;
            #pragma unroll
            for (int cx = 0; cx < 3; cx++) {
                const float pxv = -1.0f + (float)(xd - 1 + cx) * STEP;
                spy0 = fmaf(alpha0[ry * 3 + cx], py0v, spy0);
                spx0 = fmaf(alpha0[ry * 3 + cx], pxv,  spx0);
                spy1 = fmaf(alpha1[ry * 3 + cx], py1v, spy1);
                spx1 = fmaf(alpha1[ry * 3 + cx], pxv,  spx1);
            }
        }

        // it=0: covers pw*/pb/b_s + W staging visibility.
        // it>0: also guarantees prior GEMM's ldmatrix reads of z are done.
        __syncthreads();

        // ---- aggregation: 4 rows x 3 cols per channel, 2 outputs ----
        const int ot = (y0 == 0)   ? 0   : -256;
        const int ob = (y0 == 254) ? 256 : 512;
        const int xm  = (xd - 1 < 0)   ? 0   : xd - 1;
        const int xpp = (xd + 1 > 255) ? 255 : xd + 1;

        const float* cbase = x + ((size_t)b << 22) + ((size_t)(q << 4) << 16)
                           + ((size_t)y0 << 8);
        #pragma unroll 4
        for (int ci = 0; ci < 16; ci++) {
            const int c = (q << 4) + ci;
            const float* cp = cbase + ((size_t)ci << 16);
            const float* pm = cp + xm;
            const float* pc = cp + xd;
            const float* pp = cp + xpp;

            const float v00 = pm[ot],  v01 = pc[ot],  v02 = pp[ot];
            const float v10 = pm[0],   v11 = pc[0],   v12 = pp[0];
            const float v20 = pm[256], v21 = pc[256], v22 = pp[256];
            const float v30 = pm[ob],  v31 = pc[ob],  v32 = pp[ob];

            float z0 = fmaf(pw0[c], spy0, fmaf(pw1[c], spx0, pb_s[c]));
            z0 = fmaf(alpha0[0], v00, z0);
            z0 = fmaf(alpha0[1], v01, z0);
            z0 = fmaf(alpha0[2], v02, z0);
            z0 = fmaf(alpha0[3], v10, z0);
            z0 = fmaf(alpha0[4], v11, z0);
            z0 = fmaf(alpha0[5], v12, z0);
            z0 = fmaf(alpha0[6], v20, z0);
            z0 = fmaf(alpha0[7], v21, z0);
            z0 = fmaf(alpha0[8], v22, z0);

            float z1 = fmaf(pw0[c], spy1, fmaf(pw1[c], spx1, pb_s[c]));
            z1 = fmaf(alpha1[0], v10, z1);
            z1 = fmaf(alpha1[1], v11, z1);
            z1 = fmaf(alpha1[2], v12, z1);
            z1 = fmaf(alpha1[3], v20, z1);
            z1 = fmaf(alpha1[4], v21, z1);
            z1 = fmaf(alpha1[5], v22, z1);
            z1 = fmaf(alpha1[6], v30, z1);
            z1 = fmaf(alpha1[7], v31, z1);
            z1 = fmaf(alpha1[8], v32, z1);

            __nv_bfloat16 h0 = __float2bfloat16(z0);
            __nv_bfloat16 l0 = __float2bfloat16(z0 - __bfloat162float(h0));
            __nv_bfloat16 h1 = __float2bfloat16(z1);
            __nv_bfloat16 l1 = __float2bfloat16(z1 - __bfloat162float(h1));
            *(__nv_bfloat16*)(zh_c + c * ZPITCH + xl * 2)        = h0;
            *(__nv_bfloat16*)(zh_c + c * ZPITCH + (64 + xl) * 2) = h1;
            *(__nv_bfloat16*)(zl_c + c * ZPITCH + xl * 2)        = l0;
            *(__nv_bfloat16*)(zl_c + c * ZPITCH + (64 + xl) * 2) = l1;
        }
        __syncthreads();

        // ---- HMMA GEMM ----
        float acc[8][4];
        #pragma unroll
        for (int i = 0; i < 8; i++)
            #pragma unroll
            for (int j = 0; j < 4; j++) acc[i][j] = 0.0f;

        #pragma unroll
        for (int ks = 0; ks < 4; ks++) {
            const int k0 = ks << 4;
            uint32_t ah[4], al[4];
            ldm_x4(ah, wh_b + w_row + (uint32_t)k0 * 2 + w_kad);
            ldm_x4(al, wl_b + w_row + (uint32_t)k0 * 2 + w_kad);

            #pragma unroll
            for (int np = 0; np < 4; np++) {
                const uint32_t n0 = nb + (np << 4);
                const uint32_t zoff = (uint32_t)k0 * ZPITCH + z_kro + n0 * 2 + z_nad;
                uint32_t bh[4], bl[4];
                ldm_x4_t(bh, zh_b + zoff);
                ldm_x4_t(bl, zl_b + zoff);
                mma16816(acc[2 * np],     ah, bh[0], bh[1]);
                mma16816(acc[2 * np + 1], ah, bh[2], bh[3]);
                mma16816(acc[2 * np],     ah, bl[0], bl[1]);
                mma16816(acc[2 * np + 1], ah, bl[2], bl[3]);
                mma16816(acc[2 * np],     al, bh[0], bh[1]);
                mma16816(acc[2 * np + 1], al, bh[2], bh[3]);
            }
        }

        // ---- direct-STG epilogue ----
        {
            const int co_r = m0 + (lane >> 2);
            const float bv0 = b_s[co_r];
            const float bv1 = b_s[co_r + 8];
            const int yrow = y0 + (nb >> 6);
            float* obp = out + ((size_t)b << 22) + (yrow << 8) + x0g;
            float* r0p = obp + ((size_t)co_r << 16);
            float* r1p = obp + ((size_t)(co_r + 8) << 16);
            #pragma unroll
            for (int nt = 0; nt < 8; nt++) {
                const int xb = nt * 8 + 2 * (lane & 3);
                *(float2*)(r0p + xb) = make_float2(acc[nt][0] + bv0, acc[nt][1] + bv0);
                *(float2*)(r1p + xb) = make_float2(acc[nt][2] + bv1, acc[nt][3] + bv1);
            }
        }
    }
}

// ---------------------------------------------------------------------------
extern "C" void kernel_launch(void* const* d_in, const int* in_sizes, int n_in,
                              void* d_out, int out_size)
{
    const float* x       = (const float*)d_in[0];
    const float* pos_w   = (const float*)d_in[1];
    const float* pos_b   = (const float*)d_in[2];
    const float* lin_w   = (const float*)d_in[3];
    const float* att_src = (const float*)d_in[4];
    const float* att_dst = (const float*)d_in[5];
    const float* bias    = (const float*)d_in[6];
    float* out = (float*)d_out;

    gat_k1<<<512, 256>>>(x, pos_w, pos_b, lin_w, att_src, att_dst);
    gat_k2<<<512, 256>>>(x, lin_w, pos_w, pos_b, bias, out);
}

// round 17
// speedup vs baseline: 1.2614x; 1.2614x over previous
#include <cuda_runtime.h>
#include <cuda_bf16.h>
#include <cstdint>

#define NEG_SLOPE 0.2f
#define STEP (2.0f / 255.0f)

typedef unsigned long long ull;

__device__ float g_asrc[131072];
__device__ float g_adst[131072];

#define FMA2(d, a, b, c) \
    asm("fma.rn.f32x2 %0, %1, %2, %3;" : "=l"(d) : "l"(a), "l"(b), "l"(c))
#define DUP2(d, s) \
    asm("mov.b64 %0, {%1, %1};" : "=l"(d) : "r"(__float_as_uint(s)))
#define UNPACK2(lo, hi, s) do { \
    unsigned _ulo, _uhi; \
    asm("mov.b64 {%0, %1}, %2;" : "=r"(_ulo), "=r"(_uhi) : "l"(s)); \
    lo = __uint_as_float(_ulo); hi = __uint_as_float(_uhi); } while (0)

// ---------------------------------------------------------------------------
// K1: per-node a_src = xg.(W@att_src), a_dst = xg.(W@att_dst)   (unchanged)
// ---------------------------------------------------------------------------
__global__ __launch_bounds__(256) void gat_k1(
    const float* __restrict__ x,
    const float* __restrict__ pos_w,
    const float* __restrict__ pos_b,
    const float* __restrict__ lin_w,
    const float* __restrict__ att_src,
    const float* __restrict__ att_dst)
{
    __shared__ float swd[128];
    __shared__ float as_s[64], ad_s[64];
    __shared__ float pw0[64], pw1[64], pb_s[64];
    __shared__ float sc[6];

    const int tid = threadIdx.x;
    const int row = blockIdx.x;
    const int b = row >> 8;
    const int y = row & 255;

    if (tid < 64) {
        as_s[tid] = att_src[tid];
        ad_s[tid] = att_dst[tid];
        pw0[tid]  = pos_w[tid];
        pw1[tid]  = pos_w[64 + tid];
        pb_s[tid] = pos_b[tid];
    }
    __syncthreads();

    if (tid < 64) {
        float s = 0.0f, d = 0.0f;
        const float* lw = lin_w + tid * 64;
        #pragma unroll 8
        for (int co = 0; co < 64; co++) {
            float w = lw[co];
            s = fmaf(w, as_s[co], s);
            d = fmaf(w, ad_s[co], d);
        }
        swd[2 * tid]     = s;
        swd[2 * tid + 1] = d;
    }
    __syncthreads();

    if (tid < 6) {
        const int which = tid % 3;
        const int off   = (tid < 3) ? 0 : 1;
        const float* pv = (which == 0) ? pw0 : (which == 1) ? pw1 : pb_s;
        float acc = 0.0f;
        #pragma unroll 8
        for (int c = 0; c < 64; c++)
            acc = fmaf(pv[c], swd[2 * c + off], acc);
        sc[tid] = acc;
    }
    __syncthreads();

    const float py = -1.0f + (float)y * STEP;
    const float px = -1.0f + (float)tid * STEP;

    ull acc2 = 0ULL;
    const float* xp = x + (((size_t)b << 22) | ((size_t)y << 8)) + tid;
    const ull* wp = (const ull*)swd;
    #pragma unroll 8
    for (int c = 0; c < 64; c++) {
        float v = xp[(size_t)c << 16];
        ull vv; DUP2(vv, v);
        FMA2(acc2, vv, wp[c], acc2);
    }
    float s, d;
    UNPACK2(s, d, acc2);
    s += fmaf(py, sc[0], fmaf(px, sc[1], sc[2]));
    d += fmaf(py, sc[3], fmaf(px, sc[4], sc[5]));

    const int node = (b << 16) + (y << 8) + tid;
    g_asrc[node] = s;
    g_adst[node] = d;
}

// ---------------------------------------------------------------------------
// mma helpers (base PTX, sm_80+)
// ---------------------------------------------------------------------------
__device__ __forceinline__ uint32_t smem_u32(const void* p) {
    uint32_t r;
    asm("{ .reg .u64 t; cvta.to.shared.u64 t, %1; cvt.u32.u64 %0, t; }"
        : "=r"(r) : "l"(p));
    return r;
}
__device__ __forceinline__ void ldm_x4(uint32_t* r, uint32_t a) {
    asm volatile("ldmatrix.sync.aligned.m8n8.x4.shared.b16 {%0,%1,%2,%3}, [%4];"
        : "=r"(r[0]), "=r"(r[1]), "=r"(r[2]), "=r"(r[3]) : "r"(a));
}
__device__ __forceinline__ void ldm_x4_t(uint32_t* r, uint32_t a) {
    asm volatile("ldmatrix.sync.aligned.m8n8.x4.trans.shared.b16 {%0,%1,%2,%3}, [%4];"
        : "=r"(r[0]), "=r"(r[1]), "=r"(r[2]), "=r"(r[3]) : "r"(a));
}
__device__ __forceinline__ void mma16816(float* c, const uint32_t* a,
                                         uint32_t b0, uint32_t b1) {
    asm volatile(
        "mma.sync.aligned.m16n8k16.row.col.f32.bf16.bf16.f32 "
        "{%0,%1,%2,%3}, {%4,%5,%6,%7}, {%8,%9}, {%0,%1,%2,%3};"
        : "+f"(c[0]), "+f"(c[1]), "+f"(c[2]), "+f"(c[3])
        : "r"(a[0]), "r"(a[1]), "r"(a[2]), "r"(a[3]), "r"(b0), "r"(b1));
}

#define ZPITCH 272   // z tiles [c=64][node=128] bf16: 256B data + 16B pad
#define WPITCH 144   // W tiles [co=64][k=64] bf16: 128B data + 16B pad

// ---------------------------------------------------------------------------
// K2: fused, X-PAIR THREADS. block = 64 x * 2 y rows = 128 nodes, 256 threads.
//   Thread = (x-pair, 1 row, 16 channels). Per channel: 3 rows x
//   (1 float2 + 2 edge scalars) = 9 LDG -> 2 outputs = 4.5 LDG/output.
//   bf16 hi/lo pairs packed -> STS.32. node = row*64 + x. HMMA GEMM +
//   direct-STG epilogue carried over from R14 unchanged.
// ---------------------------------------------------------------------------
__global__ __launch_bounds__(256) void gat_k2(
    const float* __restrict__ x,
    const float* __restrict__ lin_w,
    const float* __restrict__ pos_w,
    const float* __restrict__ pos_b,
    const float* __restrict__ bias,
    float* __restrict__ out)
{
    __shared__ __align__(16) char tileblob[2 * 64 * ZPITCH];  // zh, zl
    __shared__ __align__(16) char wblob[2 * 64 * WPITCH];     // Wh, Wl
    __shared__ float pw0[64], pw1[64], pb_s[64], b_s[64];

    const int tid  = threadIdx.x;
    const int lane = tid & 31;
    const int wid  = tid >> 5;
    const int blk  = blockIdx.x;        // 1024
    const int b   = blk >> 9;
    const int rem = blk & 511;          // 128 y-pairs * 4 x-tiles
    const int y0  = (rem >> 2) << 1;    // even row
    const int x0g = (rem & 3) << 6;     // x tile base (64 wide)

    char* zh_c = tileblob;
    char* zl_c = tileblob + 64 * ZPITCH;
    char* wh_c = wblob;
    char* wl_c = wblob + 64 * WPITCH;

    if (tid < 64) {
        pw0[tid]  = pos_w[tid];
        pw1[tid]  = pos_w[64 + tid];
        pb_s[tid] = pos_b[tid];
        b_s[tid]  = bias[tid];
    }

    // ---- stage W hi/lo: Wh/Wl[co][k] ----
    {
        const int co = tid & 63;
        const int kq = tid >> 6;
        const float* wp = lin_w + co;
        #pragma unroll
        for (int j = 0; j < 8; j++) {
            const int k0 = kq * 16 + 2 * j;
            float w0 = wp[(size_t)k0 * 64];
            float w1 = wp[(size_t)(k0 + 1) * 64];
            __nv_bfloat162 h = __float22bfloat162_rn(make_float2(w0, w1));
            *(uint32_t*)(wh_c + co * WPITCH + k0 * 2) = *(uint32_t*)&h;
            float r0 = w0 - __bfloat162float(h.x);
            float r1 = w1 - __bfloat162float(h.y);
            __nv_bfloat162 l = __float22bfloat162_rn(make_float2(r0, r1));
            *(uint32_t*)(wl_c + co * WPITCH + k0 * 2) = *(uint32_t*)&l;
        }
    }

    // ---- per-thread geometry: warp = (row, channel-group); lane = x-pair ----
    const int rsel = wid & 1;           // 0 or 1: which of the 2 y rows
    const int c0   = (wid >> 1) << 4;   // 16 channels per thread
    const int yr   = y0 + rsel;         // this thread's output row
    const int xpL  = lane << 1;         // local even x (0..62)
    const int xp   = x0g + xpL;         // global even x

    // ---- alpha for the x-pair (18 regs), from direct LDG ----
    float alpha0[9], alpha1[9];
    {
        // a_src halo: 3 rows x 4 cols (xp-1 .. xp+2)
        float as_v[3][4];
        #pragma unroll
        for (int rr = 0; rr < 3; rr++) {
            const int yy = yr - 1 + rr;
            const bool rok = (unsigned)yy < 256u;
            #pragma unroll
            for (int cc = 0; cc < 4; cc++) {
                const int xs = xp - 1 + cc;
                float v = -1e30f;
                if (rok && (unsigned)xs < 256u)
                    v = g_asrc[(b << 16) + (yy << 8) + xs];
                as_v[rr][cc] = v;
            }
        }
        const float ad0 = g_adst[(b << 16) + (yr << 8) + xp];
        const float ad1 = g_adst[(b << 16) + (yr << 8) + xp + 1];

        float m0f = -1e30f, m1f = -1e30f;
        #pragma unroll
        for (int ry = 0; ry < 3; ry++) {
            #pragma unroll
            for (int cx = 0; cx < 3; cx++) {
                float e0 = as_v[ry][cx] + ad0;
                e0 = (e0 >= 0.0f) ? e0 : NEG_SLOPE * e0;
                alpha0[ry * 3 + cx] = e0;
                m0f = fmaxf(m0f, e0);
                float e1 = as_v[ry][cx + 1] + ad1;
                e1 = (e1 >= 0.0f) ? e1 : NEG_SLOPE * e1;
                alpha1[ry * 3 + cx] = e1;
                m1f = fmaxf(m1f, e1);
            }
        }
        float s0 = 0.0f, s1 = 0.0f;
        #pragma unroll
        for (int j = 0; j < 9; j++) {
            float p0 = expf(alpha0[j] - m0f);
            float p1 = expf(alpha1[j] - m1f);
            alpha0[j] = p0; alpha1[j] = p1;
            s0 += p0; s1 += p1;
        }
        const float i0 = 1.0f / s0, i1 = 1.0f / s1;
        #pragma unroll
        for (int j = 0; j < 9; j++) { alpha0[j] *= i0; alpha1[j] *= i1; }
    }

    // ---- PE hoist for both x ----
    float spy0 = 0.0f, spx0 = 0.0f, spy1 = 0.0f, spx1 = 0.0f;
    #pragma unroll
    for (int ry = 0; ry < 3; ry++) {
        const float pyv = -1.0f + (float)(yr - 1 + ry) * STEP;
        #pragma unroll
        for (int cx = 0; cx < 3; cx++) {
            const float px0v = -1.0f + (float)(xp - 1 + cx) * STEP;
            const float px1v = -1.0f + (float)(xp + cx) * STEP;
            spy0 = fmaf(alpha0[ry * 3 + cx], pyv,  spy0);
            spx0 = fmaf(alpha0[ry * 3 + cx], px0v, spx0);
            spy1 = fmaf(alpha1[ry * 3 + cx], pyv,  spy1);
            spx1 = fmaf(alpha1[ry * 3 + cx], px1v, spx1);
        }
    }

    // smem written by threads 0-63 (pw*/pb/b, W) read below by all threads
    __syncthreads();

    // ---- row/col offsets (clamped; OOB neutralized by alpha==0) ----
    const int rm1 = (yr == 0)   ? 0 : -256;
    const int rp1 = (yr == 255) ? 0 : 256;
    const int xlm = (xp == 0)        ? 0   : xp - 1;
    const int xrm = (xp + 2 > 255)   ? 255 : xp + 2;

    const float* cbase = x + ((size_t)b << 22) + ((size_t)c0 << 16)
                       + ((size_t)yr << 8);
    const int node0 = (rsel << 6) + xpL;   // even node; pair is node0, node0+1

    #pragma unroll 4
    for (int ci = 0; ci < 16; ci++) {
        const int c = c0 + ci;
        const float* cp = cbase + ((size_t)ci << 16);

        // 3 rows x (edge, float2, edge)
        const float* r0p = cp + rm1;
        const float* r1p = cp;
        const float* r2p = cp + rp1;
        const float  l0 = r0p[xlm];
        const float2 m0 = *(const float2*)&r0p[xp];
        const float  e0 = r0p[xrm];
        const float  l1 = r1p[xlm];
        const float2 m1 = *(const float2*)&r1p[xp];
        const float  e1 = r1p[xrm];
        const float  l2 = r2p[xlm];
        const float2 m2 = *(const float2*)&r2p[xp];
        const float  e2 = r2p[xrm];

        const float w0c = pw0[c], w1c = pw1[c], pbc = pb_s[c];

        float z0 = fmaf(w0c, spy0, fmaf(w1c, spx0, pbc));
        z0 = fmaf(alpha0[0], l0,   z0);
        z0 = fmaf(alpha0[1], m0.x, z0);
        z0 = fmaf(alpha0[2], m0.y, z0);
        z0 = fmaf(alpha0[3], l1,   z0);
        z0 = fmaf(alpha0[4], m1.x, z0);
        z0 = fmaf(alpha0[5], m1.y, z0);
        z0 = fmaf(alpha0[6], l2,   z0);
        z0 = fmaf(alpha0[7], m2.x, z0);
        z0 = fmaf(alpha0[8], m2.y, z0);

        float z1 = fmaf(w0c, spy1, fmaf(w1c, spx1, pbc));
        z1 = fmaf(alpha1[0], m0.x, z1);
        z1 = fmaf(alpha1[1], m0.y, z1);
        z1 = fmaf(alpha1[2], e0,   z1);
        z1 = fmaf(alpha1[3], m1.x, z1);
        z1 = fmaf(alpha1[4], m1.y, z1);
        z1 = fmaf(alpha1[5], e1,   z1);
        z1 = fmaf(alpha1[6], m2.x, z1);
        z1 = fmaf(alpha1[7], m2.y, z1);
        z1 = fmaf(alpha1[8], e2,   z1);

        // split to bf16 hi + residual; adjacent nodes -> packed STS.32
        __nv_bfloat162 h = __float22bfloat162_rn(make_float2(z0, z1));
        float rl0 = z0 - __bfloat162float(h.x);
        float rl1 = z1 - __bfloat162float(h.y);
        __nv_bfloat162 lo = __float22bfloat162_rn(make_float2(rl0, rl1));
        *(uint32_t*)(zh_c + c * ZPITCH + node0 * 2) = *(uint32_t*)&h;
        *(uint32_t*)(zl_c + c * ZPITCH + node0 * 2) = *(uint32_t*)&lo;
    }
    __syncthreads();

    // ---- HMMA GEMM (verified) ----
    const int m0w = (wid & 3) << 4;
    const int nb  = (wid >> 2) << 6;    // node base 0 (row y0) or 64 (row y0+1)

    const uint32_t zh_b = smem_u32(zh_c);
    const uint32_t zl_b = smem_u32(zl_c);
    const uint32_t wh_b = smem_u32(wh_c);
    const uint32_t wl_b = smem_u32(wl_c);

    const uint32_t w_row = (uint32_t)(m0w + (lane & 15)) * WPITCH;
    const uint32_t w_kad = ((lane >> 4) << 3) * 2;
    const uint32_t z_kro = (uint32_t)(lane & 15) * ZPITCH;
    const uint32_t z_nad = ((lane >> 4) << 3) * 2;

    float acc[8][4];
    #pragma unroll
    for (int i = 0; i < 8; i++)
        #pragma unroll
        for (int j = 0; j < 4; j++) acc[i][j] = 0.0f;

    #pragma unroll
    for (int ks = 0; ks < 4; ks++) {
        const int k0 = ks << 4;
        uint32_t ah[4], al[4];
        ldm_x4(ah, wh_b + w_row + (uint32_t)k0 * 2 + w_kad);
        ldm_x4(al, wl_b + w_row + (uint32_t)k0 * 2 + w_kad);

        #pragma unroll
        for (int np = 0; np < 4; np++) {
            const uint32_t n0 = nb + (np << 4);
            const uint32_t zoff = (uint32_t)k0 * ZPITCH + z_kro + n0 * 2 + z_nad;
            uint32_t bh[4], bl[4];
            ldm_x4_t(bh, zh_b + zoff);
            ldm_x4_t(bl, zl_b + zoff);
            mma16816(acc[2 * np],     ah, bh[0], bh[1]);
            mma16816(acc[2 * np + 1], ah, bh[2], bh[3]);
            mma16816(acc[2 * np],     ah, bl[0], bl[1]);
            mma16816(acc[2 * np + 1], ah, bl[2], bl[3]);
            mma16816(acc[2 * np],     al, bh[0], bh[1]);
            mma16816(acc[2 * np + 1], al, bh[2], bh[3]);
        }
    }

    // ---- direct-STG epilogue (R14) ----
    {
        const int co_r = m0w + (lane >> 2);
        const float bv0 = b_s[co_r];
        const float bv1 = b_s[co_r + 8];
        const int yrow = y0 + (nb >> 6);
        float* obp = out + ((size_t)b << 22) + (yrow << 8) + x0g;
        float* r0p = obp + ((size_t)co_r << 16);
        float* r1p = obp + ((size_t)(co_r + 8) << 16);
        #pragma unroll
        for (int nt = 0; nt < 8; nt++) {
            const int xb = nt * 8 + 2 * (lane & 3);
            *(float2*)(r0p + xb) = make_float2(acc[nt][0] + bv0, acc[nt][1] + bv0);
            *(float2*)(r1p + xb) = make_float2(acc[nt][2] + bv1, acc[nt][3] + bv1);
        }
    }
}

// ---------------------------------------------------------------------------
extern "C" void kernel_launch(void* const* d_in, const int* in_sizes, int n_in,
                              void* d_out, int out_size)
{
    const float* x       = (const float*)d_in[0];
    const float* pos_w   = (const float*)d_in[1];
    const float* pos_b   = (const float*)d_in[2];
    const float* lin_w   = (const float*)d_in[3];
    const float* att_src = (const float*)d_in[4];
    const float* att_dst = (const float*)d_in[5];
    const float* bias    = (const float*)d_in[6];
    float* out = (float*)d_out;

    gat_k1<<<512, 256>>>(x, pos_w, pos_b, lin_w, att_src, att_dst);
    gat_k2<<<1024, 256>>>(x, lin_w, pos_w, pos_b, bias, out);
}